// round 15
// baseline (speedup 1.0000x reference)
#include <cuda_runtime.h>
#include <math.h>

#define Sq  2048
#define Dd  512
#define Hh  8
#define DHh 64
#define CWw 128
#define NSPLIT 4
#define KSPL (Dd / NSPLIT)    // 128

typedef unsigned long long u64;

// ---------------- packed f32x2 helpers (sm_103a FFMA2) --------------------------
__device__ __forceinline__ void fma2(u64& d, u64 a, u64 b) {
    asm("fma.rn.f32x2 %0, %1, %2, %0;" : "+l"(d) : "l"(a), "l"(b));
}
__device__ __forceinline__ u64 pk(float lo, float hi) {
    u64 r; asm("mov.b64 %0, {%1, %2};" : "=l"(r) : "f"(lo), "f"(hi)); return r;
}
__device__ __forceinline__ float2 upk(u64 v) {
    float lo, hi; asm("mov.b64 {%0, %1}, %2;" : "=f"(lo), "=f"(hi) : "l"(v));
    return make_float2(lo, hi);
}

// ---------------- scratch (device globals) -------------------------------------
__device__ float g_cur[Sq * Dd];
__device__ float g_q[Sq * DHh];
__device__ float g_k[Sq * DHh];
__device__ float g_v[Sq * DHh];
__device__ float g_part[3][NSPLIT][Sq * DHh];
__device__ float g_pm[2][Sq];
__device__ float g_ps[2][Sq];
__device__ float g_pv[2][Sq * DHh];

// ---------------- init: cur = x -------------------------------------------------
__global__ void init_kernel(const float4* __restrict__ x) {
    int i = blockIdx.x * blockDim.x + threadIdx.x;
    ((float4*)g_cur)[i] = x[i];
}

// ---------------- qkv split-K partial GEMM (f32x2 inner loop) -------------------
__global__ __launch_bounds__(128) void qkv_partial(const float* __restrict__ Wq,
                                                   const float* __restrict__ Wk,
                                                   const float* __restrict__ Wvd, int h)
{
    __shared__ float Xs[32][36];
    __shared__ float Ws[32][68];

    const int sel = blockIdx.y;
    const int sp  = blockIdx.z;
    const float* B = (sel == 0 ? Wq : sel == 1 ? Wk : Wvd) + (size_t)h * DHh * Dd;
    float* C = &g_part[sel][sp][0];
    const int m0 = blockIdx.x * 32;
    const int kb = sp * KSPL;

    const int t  = threadIdx.x;
    const int tx = t & 15;
    const int ty = t >> 4;

    u64 acc2[2][4] = {};   // [ipair][j], pair = rows (2p, 2p+1)

    for (int k0 = kb; k0 < kb + KSPL; k0 += 32) {
        #pragma unroll
        for (int r = 0; r < 2; r++) {
            int f = t + r * 128;
            int m = f >> 3, kv = f & 7;
            float4 va = *(const float4*)&g_cur[(size_t)(m0 + m) * Dd + k0 + kv * 4];
            Xs[kv * 4 + 0][m] = va.x;
            Xs[kv * 4 + 1][m] = va.y;
            Xs[kv * 4 + 2][m] = va.z;
            Xs[kv * 4 + 3][m] = va.w;
        }
        #pragma unroll
        for (int r = 0; r < 4; r++) {
            int f = t + r * 128;
            int n = f >> 3, kv = f & 7;
            float4 vb = *(const float4*)&B[(size_t)n * Dd + k0 + kv * 4];
            Ws[kv * 4 + 0][n] = vb.x;
            Ws[kv * 4 + 1][n] = vb.y;
            Ws[kv * 4 + 2][n] = vb.z;
            Ws[kv * 4 + 3][n] = vb.w;
        }
        __syncthreads();

        #pragma unroll
        for (int k = 0; k < 32; k++) {
            float4 a4 = *(const float4*)&Xs[k][ty * 4];
            float4 b4 = *(const float4*)&Ws[k][tx * 4];
            u64 a01 = pk(a4.x, a4.y), a23 = pk(a4.z, a4.w);
            u64 bb;
            bb = pk(b4.x, b4.x); fma2(acc2[0][0], a01, bb); fma2(acc2[1][0], a23, bb);
            bb = pk(b4.y, b4.y); fma2(acc2[0][1], a01, bb); fma2(acc2[1][1], a23, bb);
            bb = pk(b4.z, b4.z); fma2(acc2[0][2], a01, bb); fma2(acc2[1][2], a23, bb);
            bb = pk(b4.w, b4.w); fma2(acc2[0][3], a01, bb); fma2(acc2[1][3], a23, bb);
        }
        __syncthreads();
    }

    #pragma unroll
    for (int p = 0; p < 2; p++) {
        float2 c0 = upk(acc2[p][0]);
        float2 c1 = upk(acc2[p][1]);
        float2 c2 = upk(acc2[p][2]);
        float2 c3 = upk(acc2[p][3]);
        float4 lo = make_float4(c0.x, c1.x, c2.x, c3.x);
        float4 hi = make_float4(c0.y, c1.y, c2.y, c3.y);
        *(float4*)&C[(size_t)(m0 + ty * 4 + 2 * p + 0) * DHh + tx * 4] = lo;
        *(float4*)&C[(size_t)(m0 + ty * 4 + 2 * p + 1) * DHh + tx * 4] = hi;
    }
}

__global__ void qkv_reduce()
{
    const int sel = blockIdx.y;
    const int i = blockIdx.x * 256 + threadIdx.x;
    float4 a = ((const float4*)&g_part[sel][0][0])[i];
    float4 b = ((const float4*)&g_part[sel][1][0])[i];
    float4 c = ((const float4*)&g_part[sel][2][0])[i];
    float4 d = ((const float4*)&g_part[sel][3][0])[i];
    float4 o;
    o.x = (a.x + b.x) + (c.x + d.x);
    o.y = (a.y + b.y) + (c.y + d.y);
    o.z = (a.z + b.z) + (c.z + d.z);
    o.w = (a.w + b.w) + (c.w + d.w);
    float* out = (sel == 0 ? g_q : sel == 1 ? g_k : g_v);
    ((float4*)out)[i] = o;
}

// ---------------- attention, window-split halves (f32x2 score + AV) -------------
#define HT   16
#define KH   144
#define KHP  68
#define PP2  148

#define ASM_K  0
#define ASM_P  (KH * KHP)            // 9792
#define ASM_Q  (ASM_P + HT * PP2)    // +2368
#define ASM_T  (ASM_Q + HT * DHh)    // 13184 floats = 52736 B

__global__ __launch_bounds__(256) void attn_half()
{
    extern __shared__ float sm[];
    float* Ks = sm + ASM_K;
    float* Ps = sm + ASM_P;
    float* Qs = sm + ASM_Q;
    float* Rs = sm + ASM_K;          // AV partials overlay Ks

    const int t    = threadIdx.x;    // 256
    const int w    = t >> 5;
    const int lane = t & 31;
    const int j0   = blockIdx.x * HT;
    const int hf   = blockIdx.y;
    const int kstart = j0 - CWw + 128 * hf;

    for (int f = t; f < KH * 16; f += 256) {
        int kk = f >> 4, d4 = f & 15;
        int gk = kstart + kk;
        float4 kv = make_float4(0.f, 0.f, 0.f, 0.f);
        if (gk >= 0 && gk < Sq) kv = ((const float4*)&g_k[(size_t)gk * DHh])[d4];
        *(float4*)&Ks[kk * KHP + d4 * 4] = kv;
    }
    {
        int q = t >> 4, d4 = t & 15;
        ((float4*)&Qs[q * DHh])[d4] = ((const float4*)&g_q[(size_t)(j0 + q) * DHh])[d4];
    }
    __syncthreads();

    const int q0 = 2 * w, q1 = 2 * w + 1;
    {
        u64 A0[5] = {}, A1[5] = {};
        #pragma unroll
        for (int d4 = 0; d4 < 16; d4++) {
            float4 qa = *(const float4*)&Qs[q0 * DHh + d4 * 4];
            float4 qb = *(const float4*)&Qs[q1 * DHh + d4 * 4];
            u64 qaxy = pk(qa.x, qa.y), qazw = pk(qa.z, qa.w);
            u64 qbxy = pk(qb.x, qb.y), qbzw = pk(qb.z, qb.w);
            #pragma unroll
            for (int jj = 0; jj < 5; jj++) {
                int kk = lane + 32 * jj;
                int kks = kk < KH - 1 ? kk : KH - 1;
                const float4 kv = *(const float4*)&Ks[kks * KHP + d4 * 4];
                u64 kxy = pk(kv.x, kv.y), kzw = pk(kv.z, kv.w);
                fma2(A0[jj], kxy, qaxy);
                fma2(A0[jj], kzw, qazw);
                fma2(A1[jj], kxy, qbxy);
                fma2(A1[jj], kzw, qbzw);
            }
        }
        float a0[5], a1[5];
        #pragma unroll
        for (int jj = 0; jj < 5; jj++) {
            float2 t0 = upk(A0[jj]);
            float2 t1 = upk(A1[jj]);
            a0[jj] = t0.x + t0.y;
            a1[jj] = t1.x + t1.y;
        }

        float m0 = -1e30f, m1 = -1e30f;
        #pragma unroll
        for (int jj = 0; jj < 5; jj++) {
            int kk = lane + 32 * jj;
            int gk = kstart + kk;
            bool gok = (gk >= 0) && (gk < Sq);
            bool v0 = gok && (kk >= q0) && (kk < q0 + 128);
            bool v1 = gok && (kk >= q1) && (kk < q1 + 128);
            a0[jj] = v0 ? a0[jj] * 0.125f : -1e30f;
            a1[jj] = v1 ? a1[jj] * 0.125f : -1e30f;
            m0 = fmaxf(m0, a0[jj]);
            m1 = fmaxf(m1, a1[jj]);
        }
        #pragma unroll
        for (int o = 16; o; o >>= 1) {
            m0 = fmaxf(m0, __shfl_xor_sync(0xffffffffu, m0, o));
            m1 = fmaxf(m1, __shfl_xor_sync(0xffffffffu, m1, o));
        }
        float s0 = 0.f, s1 = 0.f;
        #pragma unroll
        for (int jj = 0; jj < 5; jj++) {
            int kk = lane + 32 * jj;
            float e0 = __expf(a0[jj] - m0);
            float e1 = __expf(a1[jj] - m1);
            s0 += e0;
            s1 += e1;
            if (kk < KH) {
                Ps[q0 * PP2 + kk] = e0;
                Ps[q1 * PP2 + kk] = e1;
            }
        }
        #pragma unroll
        for (int o = 16; o; o >>= 1) {
            s0 += __shfl_xor_sync(0xffffffffu, s0, o);
            s1 += __shfl_xor_sync(0xffffffffu, s1, o);
        }
        if (lane == 0) {
            g_pm[hf][j0 + q0] = m0;
            g_pm[hf][j0 + q1] = m1;
            g_ps[hf][j0 + q0] = s0;
            g_ps[hf][j0 + q1] = s1;
        }
    }
    __syncthreads();

    // AV: packed p-broadcast x v-pairs
    {
        const int qh = (lane >> 4) * 8;
        const int d4 = lane & 15;
        u64 R[8][2] = {};
        #pragma unroll
        for (int i = 0; i < 18; i++) {
            int kk = w * 18 + i;
            int gk = kstart + kk;
            float4 v4 = make_float4(0.f, 0.f, 0.f, 0.f);
            if (gk >= 0 && gk < Sq)
                v4 = ((const float4*)&g_v[(size_t)gk * DHh])[d4];
            u64 vxy = pk(v4.x, v4.y), vzw = pk(v4.z, v4.w);
            #pragma unroll
            for (int qi = 0; qi < 8; qi++) {
                float p = Ps[(qh + qi) * PP2 + kk];
                u64 p2 = pk(p, p);
                fma2(R[qi][0], p2, vxy);
                fma2(R[qi][1], p2, vzw);
            }
        }
        #pragma unroll
        for (int qi = 0; qi < 8; qi++) {
            float2 xy = upk(R[qi][0]);
            float2 zw = upk(R[qi][1]);
            float4 r4 = make_float4(xy.x, xy.y, zw.x, zw.y);
            *(float4*)&Rs[(w * HT + qh + qi) * DHh + d4 * 4] = r4;
        }
    }
    __syncthreads();

    #pragma unroll
    for (int ii = 0; ii < 4; ii++) {
        int idx = t + 256 * ii;
        int q = idx >> 6, d = idx & 63;
        float s = 0.f;
        #pragma unroll
        for (int ww = 0; ww < 8; ww++) s += Rs[(ww * HT + q) * DHh + d];
        g_pv[hf][(size_t)(j0 + q) * DHh + d] = s;
    }
}

// ---------------- fused combine + up-projection + residual + renorm -------------
// R14 structure; GEMM packs tokens pairwise into f32x2.
#define WPn 68

__global__ __launch_bounds__(256) void upnorm_kernel(const float* __restrict__ Wvu,
                                                     int h, int last,
                                                     float* __restrict__ out)
{
    extern __shared__ float sm[];
    float* Ws   = sm;                     // [512][68]
    float* As   = sm + Dd * WPn;          // [16][64]
    float* RedS = As + 16 * DHh;          // [2][16]
    float* RedQ = RedS + 32;              // [2][16]

    const int t    = threadIdx.x;    // 256
    const int w    = t >> 5;
    const int lane = t & 31;
    const int wt   = w & 3;          // token group: tokens wt*4 .. wt*4+3
    const int ch   = w >> 2;         // column half
    const int m0   = blockIdx.x * 16;
    const float* Wg = Wvu + (size_t)h * Dd * DHh;

    #pragma unroll
    for (int r = 0; r < 32; r++) {
        int f = t + r * 256;
        int row = f >> 4, k4 = f & 15;
        *(float4*)&Ws[row * WPn + k4 * 4] =
            *(const float4*)&Wg[(size_t)row * DHh + k4 * 4];
    }

    #pragma unroll
    for (int ii = 0; ii < 4; ii++) {
        int idx = t + 256 * ii;
        int q = idx >> 6, d = idx & 63;
        int m = m0 + q;
        float ma = g_pm[0][m], mb = g_pm[1][m];
        float M  = fmaxf(ma, mb);
        float ca = __expf(ma - M), cb = __expf(mb - M);
        float denom = ca * g_ps[0][m] + cb * g_ps[1][m];
        float pv = ca * g_pv[0][(size_t)m * DHh + d] + cb * g_pv[1][(size_t)m * DHh + d];
        As[q * DHh + d] = pv / denom;
    }
    __syncthreads();

    // GEMM with token-paired f32x2: acc2[p][j] = (token 2p, token 2p+1)
    u64 acc2[2][8] = {};
    #pragma unroll
    for (int k4 = 0; k4 < 16; k4++) {
        float4 a[4];
        #pragma unroll
        for (int i = 0; i < 4; i++)
            a[i] = *(const float4*)&As[(wt * 4 + i) * DHh + k4 * 4];
        u64 ax0 = pk(a[0].x, a[1].x), ax1 = pk(a[2].x, a[3].x);
        u64 ay0 = pk(a[0].y, a[1].y), ay1 = pk(a[2].y, a[3].y);
        u64 az0 = pk(a[0].z, a[1].z), az1 = pk(a[2].z, a[3].z);
        u64 aw0 = pk(a[0].w, a[1].w), aw1 = pk(a[2].w, a[3].w);
        #pragma unroll
        for (int j = 0; j < 8; j++) {
            float4 wv = *(const float4*)&Ws[(ch * 256 + lane + 32 * j) * WPn + k4 * 4];
            u64 wx = pk(wv.x, wv.x), wy = pk(wv.y, wv.y);
            u64 wz = pk(wv.z, wv.z), ww = pk(wv.w, wv.w);
            fma2(acc2[0][j], ax0, wx); fma2(acc2[0][j], ay0, wy);
            fma2(acc2[0][j], az0, wz); fma2(acc2[0][j], aw0, ww);
            fma2(acc2[1][j], ax1, wx); fma2(acc2[1][j], ay1, wy);
            fma2(acc2[1][j], az1, wz); fma2(acc2[1][j], aw1, ww);
        }
    }
    // unpack into per-token accumulators
    float acc[4][8];
    #pragma unroll
    for (int p = 0; p < 2; p++)
        #pragma unroll
        for (int j = 0; j < 8; j++) {
            float2 v = upk(acc2[p][j]);
            acc[2 * p + 0][j] = v.x;
            acc[2 * p + 1][j] = v.y;
        }

    // y = acc + cur; single-pass per-token sums (s, q2), cross-warp exchange
    float cres[4][8];
    #pragma unroll
    for (int i = 0; i < 4; i++) {
        const int m = m0 + wt * 4 + i;
        float s = 0.f, q2 = 0.f;
        #pragma unroll
        for (int j = 0; j < 8; j++) {
            int n = ch * 256 + lane + 32 * j;
            cres[i][j] = g_cur[(size_t)m * Dd + n];
            float y = acc[i][j] + cres[i][j];
            acc[i][j] = y;
            s += y;
            q2 = fmaf(y, y, q2);
        }
        #pragma unroll
        for (int o = 16; o; o >>= 1) {
            s  += __shfl_xor_sync(0xffffffffu, s, o);
            q2 += __shfl_xor_sync(0xffffffffu, q2, o);
        }
        if (lane == 0) {
            RedS[ch * 16 + wt * 4 + i] = s;
            RedQ[ch * 16 + wt * 4 + i] = q2;
        }
    }
    __syncthreads();

    // renorm with m2 == 1:  new = cur + (y/m1 - 1)/sd + 1
    #pragma unroll
    for (int i = 0; i < 4; i++) {
        const int m = m0 + wt * 4 + i;
        float st = RedS[wt * 4 + i] + RedS[16 + wt * 4 + i];
        float qt = RedQ[wt * 4 + i] + RedQ[16 + wt * 4 + i];
        float m1 = st * (1.f / 512.f);
        float inv_m1 = 1.f / m1;
        float sd2 = (qt * inv_m1 * inv_m1 - 512.f) * (1.f / 511.f);
        float inv_sd = rsqrtf(sd2);

        #pragma unroll
        for (int j = 0; j < 8; j++) {
            int n = ch * 256 + lane + 32 * j;
            float nv = cres[i][j] + (acc[i][j] * inv_m1 - 1.f) * inv_sd + 1.f;
            g_cur[(size_t)m * Dd + n] = nv;
            if (last) out[(size_t)m * Dd + n] = nv * 0.125f;
        }
    }
}

// ---------------- launch ---------------------------------------------------------
extern "C" void kernel_launch(void* const* d_in, const int* in_sizes, int n_in,
                              void* d_out, int out_size)
{
    const float* x   = (const float*)d_in[0];
    const float* Wq  = (const float*)d_in[1];
    const float* Wk  = (const float*)d_in[2];
    const float* Wvd = (const float*)d_in[3];
    const float* Wvu = (const float*)d_in[4];
    float* out = (float*)d_out;

    const int attn_smem = ASM_T * 4;                           // 52736 B
    const int up_smem   = (Dd * WPn + 16 * DHh + 64) * 4;      // 143616 B
    cudaFuncSetAttribute(attn_half, cudaFuncAttributeMaxDynamicSharedMemorySize, attn_smem);
    cudaFuncSetAttribute(upnorm_kernel, cudaFuncAttributeMaxDynamicSharedMemorySize, up_smem);

    init_kernel<<<(Sq * Dd / 4) / 256, 256>>>((const float4*)x);
    for (int h = 0; h < Hh; h++) {
        qkv_partial<<<dim3(Sq / 32, 3, NSPLIT), 128>>>(Wq, Wk, Wvd, h);
        qkv_reduce<<<dim3(Sq * DHh / 4 / 256, 3), 256>>>();
        attn_half<<<dim3(Sq / HT, 2), 256, attn_smem>>>();
        upnorm_kernel<<<Sq / 16, 256, up_smem>>>(Wvu, h, h == Hh - 1 ? 1 : 0, out);
    }
}

// round 16
// speedup vs baseline: 1.2072x; 1.2072x over previous
#include <cuda_runtime.h>
#include <math.h>
#include <stdint.h>

#define Sq  2048
#define Dd  512
#define Hh  8
#define DHh 64
#define CWw 128
#define NSPLIT 4
#define KSPL (Dd / NSPLIT)    // 128

// ---------------- scratch (device globals) -------------------------------------
__device__ float g_cur[Sq * Dd];
__device__ float g_q[Sq * DHh];
__device__ float g_k[Sq * DHh];
__device__ float g_v[Sq * DHh];
__device__ float g_part[3][NSPLIT][Sq * DHh];
__device__ float g_pm[2][Sq];
__device__ float g_ps[2][Sq];
__device__ float g_pv[2][Sq * DHh];

// ---------------- tf32 helpers ----------------------------------------------------
__device__ __forceinline__ void tf32_split(float x, float& hi, float& lo) {
    asm("cvt.rna.tf32.f32 %0, %1;" : "=f"(hi) : "f"(x));
    float l = x - hi;
    asm("cvt.rna.tf32.f32 %0, %1;" : "=f"(lo) : "f"(l));
}
__device__ __forceinline__ void split4(float4 v, float4& hi, float4& lo) {
    tf32_split(v.x, hi.x, lo.x);
    tf32_split(v.y, hi.y, lo.y);
    tf32_split(v.z, hi.z, lo.z);
    tf32_split(v.w, hi.w, lo.w);
}
__device__ __forceinline__ uint32_t fu(float f) { return __float_as_uint(f); }

__device__ __forceinline__ void mma_tf32(float* c, uint32_t a0, uint32_t a1,
                                         uint32_t a2, uint32_t a3,
                                         uint32_t b0, uint32_t b1) {
    asm volatile(
        "mma.sync.aligned.m16n8k8.row.col.f32.tf32.tf32.f32 "
        "{%0,%1,%2,%3}, {%4,%5,%6,%7}, {%8,%9}, {%0,%1,%2,%3};"
        : "+f"(c[0]), "+f"(c[1]), "+f"(c[2]), "+f"(c[3])
        : "r"(a0), "r"(a1), "r"(a2), "r"(a3), "r"(b0), "r"(b1));
}

// ---------------- init: cur = x -------------------------------------------------
__global__ void init_kernel(const float4* __restrict__ x) {
    int i = blockIdx.x * blockDim.x + threadIdx.x;
    ((float4*)g_cur)[i] = x[i];
}

// ---------------- qkv split-K partial GEMM via tf32x3 tensor cores --------------
// block 128 threads = 4 warps; warp computes 16m x 32n; tile 32m x 64n x KSPL.
__global__ __launch_bounds__(128) void qkv_partial(const float* __restrict__ Wq,
                                                   const float* __restrict__ Wk,
                                                   const float* __restrict__ Wvd, int h)
{
    __shared__ float Ah[32 * 36], Al[32 * 36];
    __shared__ float Bh[64 * 36], Bl[64 * 36];

    const int sel = blockIdx.y;
    const int sp  = blockIdx.z;
    const float* B = (sel == 0 ? Wq : sel == 1 ? Wk : Wvd) + (size_t)h * DHh * Dd;
    float* C = &g_part[sel][sp][0];
    const int m0 = blockIdx.x * 32;
    const int kb = sp * KSPL;

    const int t    = threadIdx.x;
    const int w    = t >> 5;
    const int lane = t & 31;
    const int g    = lane >> 2;      // 0..7
    const int tg   = lane & 3;       // 0..3
    const int mw   = (w & 1) * 16;   // warp m offset in tile
    const int nw   = (w >> 1) * 32;  // warp n offset in tile

    float c[4][4] = {};              // [ntile][c0..c3]

    for (int k0 = kb; k0 < kb + KSPL; k0 += 32) {
        // ---- stage A (32 x 32) natural [m][k], hi/lo split
        #pragma unroll
        for (int r = 0; r < 2; r++) {
            int f = t + r * 128;
            int m = f >> 3, kv = f & 7;
            float4 va = *(const float4*)&g_cur[(size_t)(m0 + m) * Dd + k0 + kv * 4];
            float4 hi, lo;
            split4(va, hi, lo);
            *(float4*)&Ah[m * 36 + kv * 4] = hi;
            *(float4*)&Al[m * 36 + kv * 4] = lo;
        }
        // ---- stage B (64 x 32) natural [n][k], hi/lo split
        #pragma unroll
        for (int r = 0; r < 4; r++) {
            int f = t + r * 128;
            int n = f >> 3, kv = f & 7;
            float4 vb = *(const float4*)&B[(size_t)n * Dd + k0 + kv * 4];
            float4 hi, lo;
            split4(vb, hi, lo);
            *(float4*)&Bh[n * 36 + kv * 4] = hi;
            *(float4*)&Bl[n * 36 + kv * 4] = lo;
        }
        __syncthreads();

        #pragma unroll
        for (int kk = 0; kk < 32; kk += 8) {
            uint32_t a0h = fu(Ah[(mw + g)     * 36 + kk + tg]);
            uint32_t a1h = fu(Ah[(mw + g + 8) * 36 + kk + tg]);
            uint32_t a2h = fu(Ah[(mw + g)     * 36 + kk + tg + 4]);
            uint32_t a3h = fu(Ah[(mw + g + 8) * 36 + kk + tg + 4]);
            uint32_t a0l = fu(Al[(mw + g)     * 36 + kk + tg]);
            uint32_t a1l = fu(Al[(mw + g + 8) * 36 + kk + tg]);
            uint32_t a2l = fu(Al[(mw + g)     * 36 + kk + tg + 4]);
            uint32_t a3l = fu(Al[(mw + g + 8) * 36 + kk + tg + 4]);
            #pragma unroll
            for (int i = 0; i < 4; i++) {
                int n0 = nw + 8 * i;
                uint32_t b0h = fu(Bh[(n0 + g) * 36 + kk + tg]);
                uint32_t b1h = fu(Bh[(n0 + g) * 36 + kk + tg + 4]);
                uint32_t b0l = fu(Bl[(n0 + g) * 36 + kk + tg]);
                uint32_t b1l = fu(Bl[(n0 + g) * 36 + kk + tg + 4]);
                mma_tf32(c[i], a0h, a1h, a2h, a3h, b0h, b1h);
                mma_tf32(c[i], a0h, a1h, a2h, a3h, b0l, b1l);
                mma_tf32(c[i], a0l, a1l, a2l, a3l, b0h, b1h);
            }
        }
        __syncthreads();
    }

    // ---- epilogue: c0/c1 -> row (m0+mw+g), cols n0+2tg, +1; c2/c3 -> row +8
    #pragma unroll
    for (int i = 0; i < 4; i++) {
        int n0 = nw + 8 * i;
        int mA = m0 + mw + g;
        *(float2*)&C[(size_t)mA * DHh + n0 + 2 * tg]       = make_float2(c[i][0], c[i][1]);
        *(float2*)&C[(size_t)(mA + 8) * DHh + n0 + 2 * tg] = make_float2(c[i][2], c[i][3]);
    }
}

__global__ void qkv_reduce()
{
    const int sel = blockIdx.y;
    const int i = blockIdx.x * 256 + threadIdx.x;
    float4 a = ((const float4*)&g_part[sel][0][0])[i];
    float4 b = ((const float4*)&g_part[sel][1][0])[i];
    float4 c = ((const float4*)&g_part[sel][2][0])[i];
    float4 d = ((const float4*)&g_part[sel][3][0])[i];
    float4 o;
    o.x = (a.x + b.x) + (c.x + d.x);
    o.y = (a.y + b.y) + (c.y + d.y);
    o.z = (a.z + b.z) + (c.z + d.z);
    o.w = (a.w + b.w) + (c.w + d.w);
    float* out = (sel == 0 ? g_q : sel == 1 ? g_k : g_v);
    ((float4*)out)[i] = o;
}

// ---------------- attention, window-split halves (R14 proven, verbatim) ---------
#define HT   16
#define KH   144
#define KHP  68
#define PP2  148

#define ASM_K  0
#define ASM_P  (KH * KHP)            // 9792
#define ASM_Q  (ASM_P + HT * PP2)    // +2368
#define ASM_T  (ASM_Q + HT * DHh)    // 13184 floats = 52736 B

__global__ __launch_bounds__(256) void attn_half()
{
    extern __shared__ float sm[];
    float* Ks = sm + ASM_K;
    float* Ps = sm + ASM_P;
    float* Qs = sm + ASM_Q;
    float* Rs = sm + ASM_K;          // AV partials overlay Ks (8192 <= 9792)

    const int t    = threadIdx.x;    // 256
    const int w    = t >> 5;
    const int lane = t & 31;
    const int j0   = blockIdx.x * HT;
    const int hf   = blockIdx.y;
    const int kstart = j0 - CWw + 128 * hf;

    for (int f = t; f < KH * 16; f += 256) {
        int kk = f >> 4, d4 = f & 15;
        int gk = kstart + kk;
        float4 kv = make_float4(0.f, 0.f, 0.f, 0.f);
        if (gk >= 0 && gk < Sq) kv = ((const float4*)&g_k[(size_t)gk * DHh])[d4];
        *(float4*)&Ks[kk * KHP + d4 * 4] = kv;
    }
    {
        int q = t >> 4, d4 = t & 15;
        ((float4*)&Qs[q * DHh])[d4] = ((const float4*)&g_q[(size_t)(j0 + q) * DHh])[d4];
    }
    __syncthreads();

    const int q0 = 2 * w, q1 = 2 * w + 1;
    {
        float a0[5] = {}, a1[5] = {};
        #pragma unroll
        for (int d4 = 0; d4 < 16; d4++) {
            float4 qa = *(const float4*)&Qs[q0 * DHh + d4 * 4];
            float4 qb = *(const float4*)&Qs[q1 * DHh + d4 * 4];
            #pragma unroll
            for (int jj = 0; jj < 5; jj++) {
                int kk = lane + 32 * jj;
                int kks = kk < KH - 1 ? kk : KH - 1;
                const float4 kv = *(const float4*)&Ks[kks * KHP + d4 * 4];
                a0[jj] = fmaf(kv.x, qa.x, fmaf(kv.y, qa.y, fmaf(kv.z, qa.z, fmaf(kv.w, qa.w, a0[jj]))));
                a1[jj] = fmaf(kv.x, qb.x, fmaf(kv.y, qb.y, fmaf(kv.z, qb.z, fmaf(kv.w, qb.w, a1[jj]))));
            }
        }
        float m0 = -1e30f, m1 = -1e30f;
        #pragma unroll
        for (int jj = 0; jj < 5; jj++) {
            int kk = lane + 32 * jj;
            int gk = kstart + kk;
            bool gok = (gk >= 0) && (gk < Sq);
            bool v0 = gok && (kk >= q0) && (kk < q0 + 128);
            bool v1 = gok && (kk >= q1) && (kk < q1 + 128);
            a0[jj] = v0 ? a0[jj] * 0.125f : -1e30f;
            a1[jj] = v1 ? a1[jj] * 0.125f : -1e30f;
            m0 = fmaxf(m0, a0[jj]);
            m1 = fmaxf(m1, a1[jj]);
        }
        #pragma unroll
        for (int o = 16; o; o >>= 1) {
            m0 = fmaxf(m0, __shfl_xor_sync(0xffffffffu, m0, o));
            m1 = fmaxf(m1, __shfl_xor_sync(0xffffffffu, m1, o));
        }
        float s0 = 0.f, s1 = 0.f;
        #pragma unroll
        for (int jj = 0; jj < 5; jj++) {
            int kk = lane + 32 * jj;
            float e0 = __expf(a0[jj] - m0);
            float e1 = __expf(a1[jj] - m1);
            s0 += e0;
            s1 += e1;
            if (kk < KH) {
                Ps[q0 * PP2 + kk] = e0;
                Ps[q1 * PP2 + kk] = e1;
            }
        }
        #pragma unroll
        for (int o = 16; o; o >>= 1) {
            s0 += __shfl_xor_sync(0xffffffffu, s0, o);
            s1 += __shfl_xor_sync(0xffffffffu, s1, o);
        }
        if (lane == 0) {
            g_pm[hf][j0 + q0] = m0;
            g_pm[hf][j0 + q1] = m1;
            g_ps[hf][j0 + q0] = s0;
            g_ps[hf][j0 + q1] = s1;
        }
    }
    __syncthreads();

    {
        const int qh = (lane >> 4) * 8;
        const int d4 = lane & 15;
        float4 r[8] = {};
        #pragma unroll
        for (int i = 0; i < 18; i++) {
            int kk = w * 18 + i;
            int gk = kstart + kk;
            float4 v4 = make_float4(0.f, 0.f, 0.f, 0.f);
            if (gk >= 0 && gk < Sq)
                v4 = ((const float4*)&g_v[(size_t)gk * DHh])[d4];
            #pragma unroll
            for (int qi = 0; qi < 8; qi++) {
                float p = Ps[(qh + qi) * PP2 + kk];
                r[qi].x = fmaf(p, v4.x, r[qi].x);
                r[qi].y = fmaf(p, v4.y, r[qi].y);
                r[qi].z = fmaf(p, v4.z, r[qi].z);
                r[qi].w = fmaf(p, v4.w, r[qi].w);
            }
        }
        #pragma unroll
        for (int qi = 0; qi < 8; qi++)
            *(float4*)&Rs[(w * HT + qh + qi) * DHh + d4 * 4] = r[qi];
    }
    __syncthreads();

    #pragma unroll
    for (int ii = 0; ii < 4; ii++) {
        int idx = t + 256 * ii;
        int q = idx >> 6, d = idx & 63;
        float s = 0.f;
        #pragma unroll
        for (int ww = 0; ww < 8; ww++) s += Rs[(ww * HT + q) * DHh + d];
        g_pv[hf][(size_t)(j0 + q) * DHh + d] = s;
    }
}

// ---------------- fused combine + up-projection + residual + renorm -------------
// R14 proven verbatim: 16 tokens/block, warp = 4 tokens x 256 cols, m2==1 renorm.
#define WPn 68

__global__ __launch_bounds__(256) void upnorm_kernel(const float* __restrict__ Wvu,
                                                     int h, int last,
                                                     float* __restrict__ out)
{
    extern __shared__ float sm[];
    float* Ws   = sm;                     // [512][68]
    float* As   = sm + Dd * WPn;          // [16][64]
    float* RedS = As + 16 * DHh;          // [2][16]
    float* RedQ = RedS + 32;              // [2][16]

    const int t    = threadIdx.x;    // 256
    const int w    = t >> 5;
    const int lane = t & 31;
    const int wt   = w & 3;
    const int ch   = w >> 2;
    const int m0   = blockIdx.x * 16;
    const float* Wg = Wvu + (size_t)h * Dd * DHh;

    #pragma unroll
    for (int r = 0; r < 32; r++) {
        int f = t + r * 256;
        int row = f >> 4, k4 = f & 15;
        *(float4*)&Ws[row * WPn + k4 * 4] =
            *(const float4*)&Wg[(size_t)row * DHh + k4 * 4];
    }

    #pragma unroll
    for (int ii = 0; ii < 4; ii++) {
        int idx = t + 256 * ii;
        int q = idx >> 6, d = idx & 63;
        int m = m0 + q;
        float ma = g_pm[0][m], mb = g_pm[1][m];
        float M  = fmaxf(ma, mb);
        float ca = __expf(ma - M), cb = __expf(mb - M);
        float denom = ca * g_ps[0][m] + cb * g_ps[1][m];
        float pv = ca * g_pv[0][(size_t)m * DHh + d] + cb * g_pv[1][(size_t)m * DHh + d];
        As[q * DHh + d] = pv / denom;
    }
    __syncthreads();

    float acc[4][8] = {};
    #pragma unroll
    for (int k4 = 0; k4 < 16; k4++) {
        float4 a[4];
        #pragma unroll
        for (int i = 0; i < 4; i++)
            a[i] = *(const float4*)&As[(wt * 4 + i) * DHh + k4 * 4];
        #pragma unroll
        for (int j = 0; j < 8; j++) {
            float4 wv = *(const float4*)&Ws[(ch * 256 + lane + 32 * j) * WPn + k4 * 4];
            #pragma unroll
            for (int i = 0; i < 4; i++)
                acc[i][j] = fmaf(a[i].x, wv.x, fmaf(a[i].y, wv.y,
                             fmaf(a[i].z, wv.z, fmaf(a[i].w, wv.w, acc[i][j]))));
        }
    }

    float cres[4][8];
    #pragma unroll
    for (int i = 0; i < 4; i++) {
        const int m = m0 + wt * 4 + i;
        float s = 0.f, q2 = 0.f;
        #pragma unroll
        for (int j = 0; j < 8; j++) {
            int n = ch * 256 + lane + 32 * j;
            cres[i][j] = g_cur[(size_t)m * Dd + n];
            float y = acc[i][j] + cres[i][j];
            acc[i][j] = y;
            s += y;
            q2 = fmaf(y, y, q2);
        }
        #pragma unroll
        for (int o = 16; o; o >>= 1) {
            s  += __shfl_xor_sync(0xffffffffu, s, o);
            q2 += __shfl_xor_sync(0xffffffffu, q2, o);
        }
        if (lane == 0) {
            RedS[ch * 16 + wt * 4 + i] = s;
            RedQ[ch * 16 + wt * 4 + i] = q2;
        }
    }
    __syncthreads();

    #pragma unroll
    for (int i = 0; i < 4; i++) {
        const int m = m0 + wt * 4 + i;
        float st = RedS[wt * 4 + i] + RedS[16 + wt * 4 + i];
        float qt = RedQ[wt * 4 + i] + RedQ[16 + wt * 4 + i];
        float m1 = st * (1.f / 512.f);
        float inv_m1 = 1.f / m1;
        float sd2 = (qt * inv_m1 * inv_m1 - 512.f) * (1.f / 511.f);
        float inv_sd = rsqrtf(sd2);

        #pragma unroll
        for (int j = 0; j < 8; j++) {
            int n = ch * 256 + lane + 32 * j;
            float nv = cres[i][j] + (acc[i][j] * inv_m1 - 1.f) * inv_sd + 1.f;
            g_cur[(size_t)m * Dd + n] = nv;
            if (last) out[(size_t)m * Dd + n] = nv * 0.125f;
        }
    }
}

// ---------------- launch ---------------------------------------------------------
extern "C" void kernel_launch(void* const* d_in, const int* in_sizes, int n_in,
                              void* d_out, int out_size)
{
    const float* x   = (const float*)d_in[0];
    const float* Wq  = (const float*)d_in[1];
    const float* Wk  = (const float*)d_in[2];
    const float* Wvd = (const float*)d_in[3];
    const float* Wvu = (const float*)d_in[4];
    float* out = (float*)d_out;

    const int attn_smem = ASM_T * 4;                           // 52736 B
    const int up_smem   = (Dd * WPn + 16 * DHh + 64) * 4;      // 143616 B
    cudaFuncSetAttribute(attn_half, cudaFuncAttributeMaxDynamicSharedMemorySize, attn_smem);
    cudaFuncSetAttribute(upnorm_kernel, cudaFuncAttributeMaxDynamicSharedMemorySize, up_smem);

    init_kernel<<<(Sq * Dd / 4) / 256, 256>>>((const float4*)x);
    for (int h = 0; h < Hh; h++) {
        qkv_partial<<<dim3(Sq / 32, 3, NSPLIT), 128>>>(Wq, Wk, Wvd, h);
        qkv_reduce<<<dim3(Sq * DHh / 4 / 256, 3), 256>>>();
        attn_half<<<dim3(Sq / HT, 2), 256, attn_smem>>>();
        upnorm_kernel<<<Sq / 16, 256, up_smem>>>(Wvu, h, h == Hh - 1 ? 1 : 0, out);
    }
}